// round 4
// baseline (speedup 1.0000x reference)
#include <cuda_runtime.h>

// CELossWithLS: focal-weighted label-smoothed CE, single fused kernel.
// logits: [B*S, C] f32 (C = 10000), target: [B*S] int32, out: scalar f32.
//
// per_tok = -( 1e-5 * sum_i (1-p_i)^3 * logs_i  +  0.9 * (1-p_t)^3 * logs_t )
// sum_i (1-p)^3 logs = (Sx - C*L) - 3*(B1/A1 - L) + O(1.5e-5 abs)
// with A1 = sum e^x, B1 = sum x e^x, L = log(A1). Dropped p^2/p^3 terms carry
// the 1e-5 smoothing weight: ~2e-6 relative vs per-token loss ~8.8.
// Validated round 3: rel_err printed as 0.0.
//
// Single kernel: per-row partials -> __device__ scratch (every slot rewritten
// each call, so no init kernel), arrival counter -> last CTA reduces + writes
// d_out + resets counter (deterministic across graph replays).

#define NCLASS  10000
#define NVEC    (NCLASS / 4)   // 2500 float4 per row
#define THREADS 256
#define MAXTOK  16384

__device__ float        g_per[MAXTOK];
__device__ unsigned int g_arrive = 0;   // always 0 at kernel entry (reset by last CTA)

__global__ __launch_bounds__(THREADS, 1) void ce_fused(
    const float* __restrict__ logits,
    const int*   __restrict__ target,
    float*       __restrict__ out,
    const int    ntok)
{
    const int row = blockIdx.x;
    const int tgt = __ldg(&target[row]);

    const float4* __restrict__ p =
        reinterpret_cast<const float4*>(logits) + (size_t)row * NVEC;

    float sx = 0.0f;   // sum x
    float a1 = 0.0f;   // sum e^x
    float b1 = 0.0f;   // sum x * e^x

    #pragma unroll 4
    for (int i = threadIdx.x; i < NVEC; i += THREADS) {
        float4 v = p[i];
        float e;
        e = __expf(v.x); sx += v.x; a1 += e; b1 = fmaf(v.x, e, b1);
        e = __expf(v.y); sx += v.y; a1 += e; b1 = fmaf(v.y, e, b1);
        e = __expf(v.z); sx += v.z; a1 += e; b1 = fmaf(v.z, e, b1);
        e = __expf(v.w); sx += v.w; a1 += e; b1 = fmaf(v.w, e, b1);
    }

    // intra-warp tree reduce (3 values)
    #pragma unroll
    for (int o = 16; o > 0; o >>= 1) {
        sx += __shfl_down_sync(0xffffffffu, sx, o);
        a1 += __shfl_down_sync(0xffffffffu, a1, o);
        b1 += __shfl_down_sync(0xffffffffu, b1, o);
    }

    __shared__ float s_sx[THREADS / 32];
    __shared__ float s_a1[THREADS / 32];
    __shared__ float s_b1[THREADS / 32];
    __shared__ int   s_last;
    const int lane = threadIdx.x & 31;
    const int wrp  = threadIdx.x >> 5;
    if (lane == 0) { s_sx[wrp] = sx; s_a1[wrp] = a1; s_b1[wrp] = b1; }
    __syncthreads();

    if (threadIdx.x == 0) {
        float SX = 0.0f, A1 = 0.0f, B1 = 0.0f;
        #pragma unroll
        for (int k = 0; k < THREADS / 32; k++) {
            SX += s_sx[k]; A1 += s_a1[k]; B1 += s_b1[k];
        }
        float per_tok = 0.0f;
        if (tgt != -1) {
            // accurate log: its error is multiplied by C=1e4 in (SX - C*L)
            float L  = logf(A1);
            float S3 = (SX - (float)NCLASS * L) - 3.0f * (B1 / A1 - L);
            per_tok = -1e-5f * S3;
            if (tgt >= 0 && tgt < NCLASS) {      // bound-checked gather
                float xt = __ldg(&logits[(size_t)row * NCLASS + tgt]);
                float lt = xt - L;
                float pt = __expf(lt);
                float om = 1.0f - pt;
                per_tok -= 0.9f * om * om * om * lt;
            }
        }
        g_per[row] = per_tok;

        __threadfence();                          // release partial
        unsigned prev = atomicAdd(&g_arrive, 1u);
        s_last = (prev == (unsigned)(ntok - 1)) ? 1 : 0;
    }
    __syncthreads();

    if (s_last) {
        __threadfence();                          // acquire all partials
        double acc = 0.0;
        int    cnt = 0;
        for (int i = threadIdx.x; i < ntok; i += THREADS) {
            acc += (double)g_per[i];
            cnt += (__ldg(&target[i]) != -1) ? 1 : 0;
        }
        #pragma unroll
        for (int o = 16; o > 0; o >>= 1) {
            acc += __shfl_down_sync(0xffffffffu, acc, o);
            cnt += __shfl_down_sync(0xffffffffu, cnt, o);
        }
        __shared__ double f_acc[THREADS / 32];
        __shared__ int    f_cnt[THREADS / 32];
        if (lane == 0) { f_acc[wrp] = acc; f_cnt[wrp] = cnt; }
        __syncthreads();
        if (threadIdx.x == 0) {
            double A = 0.0; int Cn = 0;
            #pragma unroll
            for (int k = 0; k < THREADS / 32; k++) { A += f_acc[k]; Cn += f_cnt[k]; }
            out[0] = (float)(A / (double)Cn);
            g_arrive = 0;                         // reset for next replay
        }
    }
}

extern "C" void kernel_launch(void* const* d_in, const int* in_sizes, int n_in,
                              void* d_out, int out_size)
{
    const float* logits = (const float*)d_in[0];
    const int*   target = (const int*)d_in[1];
    const int ntok = in_sizes[1];          // B*S tokens

    ce_fused<<<ntok, THREADS>>>(logits, target, (float*)d_out, ntok);
}

// round 5
// speedup vs baseline: 1.1256x; 1.1256x over previous
#include <cuda_runtime.h>

// CELossWithLS: focal-weighted label-smoothed CE, single fused kernel.
// logits: [B*S, C] f32 (C = 10000), target: [B*S] int32, out: scalar f32.
//
// per_tok = -( 1e-5 * sum_i (1-p_i)^3 * logs_i  +  0.9 * (1-p_t)^3 * logs_t )
// sum_i (1-p)^3 logs = (Sx - C*L) - 3*(B1/A1 - L) + O(1.5e-5 abs)
// with A1 = sum e^x, B1 = sum x e^x, L = log(A1). Dropped p^2/p^3 terms carry
// the 1e-5 smoothing weight: ~2e-6 relative. Validated r3/r4: rel_err = 0.0.
//
// R4 lesson: unroll 4 -> 56 regs -> 4 CTAs/SM (32 warps) -> latency-bound at
// DRAM=54.5%. This round: unroll 2 + __launch_bounds__(256,8) -> 32-reg budget
// -> 64 warps/SM. Outstanding bytes: 64 warps x 2 LDG.128 x 512B = 64KB/SM,
// well above the ~18KB needed to cover DRAM latency at the HBM roof.

#define NCLASS  10000
#define NVEC    (NCLASS / 4)   // 2500 float4 per row
#define THREADS 256
#define MAXTOK  16384

__device__ float        g_per[MAXTOK];
__device__ unsigned int g_arrive = 0;   // always 0 at kernel entry (reset by last CTA)

__global__ __launch_bounds__(THREADS, 8) void ce_fused(
    const float* __restrict__ logits,
    const int*   __restrict__ target,
    float*       __restrict__ out,
    const int    ntok)
{
    const int row = blockIdx.x;
    const int tgt = __ldg(&target[row]);

    const float4* __restrict__ p =
        reinterpret_cast<const float4*>(logits) + (size_t)row * NVEC;

    float sx = 0.0f;   // sum x
    float a1 = 0.0f;   // sum e^x
    float b1 = 0.0f;   // sum x * e^x

    #pragma unroll 2
    for (int i = threadIdx.x; i < NVEC; i += THREADS) {
        float4 v = p[i];
        float e;
        e = __expf(v.x); sx += v.x; a1 += e; b1 = fmaf(v.x, e, b1);
        e = __expf(v.y); sx += v.y; a1 += e; b1 = fmaf(v.y, e, b1);
        e = __expf(v.z); sx += v.z; a1 += e; b1 = fmaf(v.z, e, b1);
        e = __expf(v.w); sx += v.w; a1 += e; b1 = fmaf(v.w, e, b1);
    }

    // intra-warp tree reduce (3 values)
    #pragma unroll
    for (int o = 16; o > 0; o >>= 1) {
        sx += __shfl_down_sync(0xffffffffu, sx, o);
        a1 += __shfl_down_sync(0xffffffffu, a1, o);
        b1 += __shfl_down_sync(0xffffffffu, b1, o);
    }

    __shared__ float s_sx[THREADS / 32];
    __shared__ float s_a1[THREADS / 32];
    __shared__ float s_b1[THREADS / 32];
    __shared__ int   s_last;
    const int lane = threadIdx.x & 31;
    const int wrp  = threadIdx.x >> 5;
    if (lane == 0) { s_sx[wrp] = sx; s_a1[wrp] = a1; s_b1[wrp] = b1; }
    __syncthreads();

    if (threadIdx.x == 0) {
        float SX = 0.0f, A1 = 0.0f, B1 = 0.0f;
        #pragma unroll
        for (int k = 0; k < THREADS / 32; k++) {
            SX += s_sx[k]; A1 += s_a1[k]; B1 += s_b1[k];
        }
        float per_tok = 0.0f;
        if (tgt != -1) {
            // accurate log: its error is multiplied by C=1e4 in (SX - C*L)
            float L  = logf(A1);
            float S3 = (SX - (float)NCLASS * L) - 3.0f * (B1 / A1 - L);
            per_tok = -1e-5f * S3;
            if (tgt >= 0 && tgt < NCLASS) {      // bound-checked gather
                float xt = __ldg(&logits[(size_t)row * NCLASS + tgt]);
                float lt = xt - L;
                float pt = __expf(lt);
                float om = 1.0f - pt;
                per_tok -= 0.9f * om * om * om * lt;
            }
        }
        g_per[row] = per_tok;

        __threadfence();                          // release partial
        unsigned prev = atomicAdd(&g_arrive, 1u);
        s_last = (prev == (unsigned)(ntok - 1)) ? 1 : 0;
    }
    __syncthreads();

    if (s_last) {
        __threadfence();                          // acquire all partials
        double acc = 0.0;
        int    cnt = 0;
        for (int i = threadIdx.x; i < ntok; i += THREADS) {
            acc += (double)g_per[i];
            cnt += (__ldg(&target[i]) != -1) ? 1 : 0;
        }
        #pragma unroll
        for (int o = 16; o > 0; o >>= 1) {
            acc += __shfl_down_sync(0xffffffffu, acc, o);
            cnt += __shfl_down_sync(0xffffffffu, cnt, o);
        }
        __shared__ double f_acc[THREADS / 32];
        __shared__ int    f_cnt[THREADS / 32];
        if (lane == 0) { f_acc[wrp] = acc; f_cnt[wrp] = cnt; }
        __syncthreads();
        if (threadIdx.x == 0) {
            double A = 0.0; int Cn = 0;
            #pragma unroll
            for (int k = 0; k < THREADS / 32; k++) { A += f_acc[k]; Cn += f_cnt[k]; }
            out[0] = (float)(A / (double)Cn);
            g_arrive = 0;                         // reset for next replay
        }
    }
}

extern "C" void kernel_launch(void* const* d_in, const int* in_sizes, int n_in,
                              void* d_out, int out_size)
{
    const float* logits = (const float*)d_in[0];
    const int*   target = (const int*)d_in[1];
    const int ntok = in_sizes[1];          // B*S tokens

    ce_fused<<<ntok, THREADS>>>(logits, target, (float*)d_out, ntok);
}